// round 11
// baseline (speedup 1.0000x reference)
#include <cuda_runtime.h>

#define Bn 64
#define Dd 32
#define Hh 48
#define Ww 48
#define NA (Dd*Hh*Ww)        /* 73728 anchors per batch */
#define TOPK 60
#define NMS_TOPK 20
#define THRESH 0.15f
#define NMS_T 0.05f
#define NBINS 4096
#define NT 1024
#define HF4 (NA/4/2)         /* 9216 float4 per half */
#define CHUNK 9              /* 9 float4 per thread, MLP=9 */
#define CAND_FB 2304
#define T_RAW 2.9f

__device__ __forceinline__ unsigned fkey(float f) {
    unsigned u = __float_as_uint(f);
    return u ^ ((u & 0x80000000u) ? 0xFFFFFFFFu : 0x80000000u);
}
__device__ __forceinline__ float finv(unsigned k) {
    unsigned u = (k & 0x80000000u) ? (k ^ 0x80000000u) : ~k;
    return __uint_as_float(u);
}
__device__ __forceinline__ unsigned smem_u32(const void* p) {
    unsigned a;
    asm("{ .reg .u64 t; cvta.to.shared.u64 t, %1; cvt.u32.u64 %0, t; }"
        : "=r"(a) : "l"(p));
    return a;
}
__device__ __forceinline__ unsigned mapa0(unsigned addr) {
    unsigned r;
    asm("mapa.shared::cluster.u32 %0, %1, 0;" : "=r"(r) : "r"(addr));
    return r;
}
__device__ __forceinline__ int dsmem_inc(unsigned addr) {
    int old;
    asm volatile("atom.relaxed.cluster.shared::cluster.add.u32 %0, [%1], 1;"
                 : "=r"(old) : "r"(addr) : "memory");
    return old;
}
__device__ __forceinline__ void dsmem_st64(unsigned addr, unsigned long long v) {
    asm volatile("st.shared::cluster.u64 [%0], %1;" :: "r"(addr), "l"(v) : "memory");
}

__global__ __launch_bounds__(NT, 1) __cluster_dims__(2, 1, 1)
void detclu(const float* __restrict__ Cls,
            const float* __restrict__ Shp,
            const float* __restrict__ Off,
            float* __restrict__ out)
{
    const int b    = blockIdx.y;
    const int tid  = threadIdx.x;
    unsigned rank;
    asm("mov.u32 %0, %%cluster_ctarank;" : "=r"(rank));

    __shared__ int s_cnt;
    __shared__ union UU {
        unsigned hist[NBINS];                 /* 16 KB, fallback only */
        unsigned long long cand[CAND_FB];     /* 18.4 KB */
    } u;
    __shared__ int partial[NT];
    __shared__ int thr_bin;
    __shared__ int cand_cnt;
    __shared__ float s_score[TOPK];
    __shared__ float s_ctr[TOPK][3];
    __shared__ float s_ext[TOPK][3];
    __shared__ unsigned char s_valid[TOPK];
    __shared__ unsigned long long s_mask[TOPK];
    __shared__ unsigned long long s_keep;

    const float4* c4 = (const float4*)(Cls + (size_t)b * NA);
    float* ob = out + (size_t)b * TOPK * 8;

    if (tid == 0) s_cnt = 0;
    if (tid < TOPK) s_mask[tid] = 0ull;

    // remote (rank-0) addresses for candidate push
    const unsigned cnt_r  = mapa0(smem_u32(&s_cnt));
    const unsigned cand_r = mapa0(smem_u32(u.cand));

    // ---- issue scan loads NOW (in flight across the cluster barrier) ----
    const int hbase = (int)rank * HF4;
    float4 q[CHUNK];
    #pragma unroll
    for (int j = 0; j < CHUNK; j++) q[j] = c4[hbase + j * NT + tid];

    __syncthreads();                                   // s_cnt init done (CTA-local)
    asm volatile("barrier.cluster.arrive.aligned;" ::: "memory");   // B1
    asm volatile("barrier.cluster.wait.aligned;"   ::: "memory");

    // ---- branchless hit detection, push via DSMEM into rank-0 smem ----
    {
        unsigned hm = 0;
        #pragma unroll
        for (int j = 0; j < CHUNK; j++) {
            float mx = fmaxf(fmaxf(q[j].x, q[j].y), fmaxf(q[j].z, q[j].w));
            hm |= (mx > T_RAW) ? (1u << j) : 0u;
        }
        if (hm) {                                      // rare (~5% of threads)
            #pragma unroll
            for (int j = 0; j < CHUNK; j++) {
                if (hm & (1u << j)) {
                    int gi = hbase + j * NT + tid;
                    #pragma unroll
                    for (int k = 0; k < 4; k++) {
                        float f = (k == 0) ? q[j].x : (k == 1) ? q[j].y
                                : (k == 2) ? q[j].z : q[j].w;
                        if (f > T_RAW) {
                            int off = dsmem_inc(cnt_r);
                            if (off < CAND_FB) {
                                unsigned idx = (unsigned)(gi * 4 + k);
                                unsigned long long key =
                                    ((unsigned long long)fkey(f) << 32) | (unsigned)(~idx);
                                dsmem_st64(cand_r + (unsigned)off * 8u, key);
                            }
                        }
                    }
                }
            }
        }
    }

    // partner prefills -1 output while pushes drain
    if (rank == 1) {
        if (tid < TOPK * 8) ob[tid] = -1.0f;
    }

    asm volatile("barrier.cluster.arrive.aligned;" ::: "memory");   // B2
    asm volatile("barrier.cluster.wait.aligned;"   ::: "memory");
    if (rank == 1) return;

    // ================= selector (rank 0): select + NMS + write ===================
    int c = s_cnt;
    const bool fast = (c >= TOPK) && (c <= NT);

    if (fast) {
        // ---------- FAST PATH: rank-select top-60, gather boxes ----------
        if (tid < c) {
            unsigned long long k0 = u.cand[tid];

            // scattered box loads issued NOW; overlap with the rank loop
            unsigned idx = ~(unsigned)(k0 & 0xFFFFFFFFull);
            int z = (int)idx / (Hh * Ww);
            int rem = (int)idx % (Hh * Ww);
            float az = (float)z, ay = (float)(rem / Ww), ax = (float)(rem % Ww);
            size_t base3 = (size_t)b * 3 * NA + idx;
            float o0 = Off[base3], o1 = Off[base3 + NA], o2 = Off[base3 + 2 * NA];
            float h0 = Shp[base3], h1 = Shp[base3 + NA], h2 = Shp[base3 + 2 * NA];

            int r0 = 0;
            #pragma unroll 4
            for (int j = 0; j < c; j++)                // broadcast LDS
                r0 += (u.cand[j] > k0) ? 1 : 0;

            if (r0 < TOPK) {
                float raw = finv((unsigned)(k0 >> 32));
                float sc  = 1.0f / (1.0f + __expf(-raw));
                s_score[r0] = sc;
                s_valid[r0] = (sc > THRESH) ? 1 : 0;
                s_ctr[r0][0] = (az + o0) * 2.0f;       // stride = (2,2,2)
                s_ctr[r0][1] = (ay + o1) * 2.0f;
                s_ctr[r0][2] = (ax + o2) * 2.0f;
                s_ext[r0][0] = 2.0f * h0;
                s_ext[r0][1] = 2.0f * h1;
                s_ext[r0][2] = 2.0f * h2;
            }
        }
        __syncthreads();
    } else {
        // -------- exact histogram fallback over the whole batch (never hit) ------
        const int lane = tid & 31;
        for (int i = tid; i < NBINS; i += NT) u.hist[i] = 0u;
        if (tid == 0) { thr_bin = 0; cand_cnt = 0; }
        __syncthreads();
        for (int i = tid; i < NA / 4; i += NT) {
            float4 v = c4[i];
            #pragma unroll
            for (int k = 0; k < 4; k++) {
                float f = (k == 0) ? v.x : (k == 1) ? v.y : (k == 2) ? v.z : v.w;
                int bin = (int)(fkey(f) >> 20);
                unsigned m = __match_any_sync(0xFFFFFFFFu, bin);
                if (lane == (__ffs(m) - 1))
                    atomicAdd(&u.hist[bin], (unsigned)__popc(m));
            }
        }
        __syncthreads();
        const int BPT = NBINS / NT;                    // 4
        int hb = tid * BPT;
        int loc = 0;
        #pragma unroll
        for (int j = 0; j < BPT; j++) loc += (int)u.hist[hb + j];
        partial[tid] = loc;
        __syncthreads();
        if (tid == 0) {
            int run = 0;
            for (int t = NT - 1; t >= 0; t--) { int p = partial[t]; partial[t] = run; run += p; }
        }
        __syncthreads();
        {
            int cum_above = partial[tid];
            if (cum_above < TOPK && cum_above + loc >= TOPK) {
                int cum = cum_above;
                for (int j = BPT - 1; j >= 0; j--) {
                    cum += (int)u.hist[hb + j];
                    if (cum >= TOPK) { thr_bin = hb + j; break; }
                }
            }
        }
        __syncthreads();
        const unsigned klow = (unsigned)thr_bin << 20;
        __syncthreads();                               // done with hist before reuse
        for (int i = tid; i < NA / 4; i += NT) {
            float4 v = c4[i];
            #pragma unroll
            for (int k = 0; k < 4; k++) {
                float f = (k == 0) ? v.x : (k == 1) ? v.y : (k == 2) ? v.z : v.w;
                unsigned key = fkey(f);
                if (key >= klow) {
                    int pos = atomicAdd(&cand_cnt, 1);
                    if (pos < CAND_FB) {
                        unsigned idx = (unsigned)(i * 4 + k);
                        u.cand[pos] = ((unsigned long long)key << 32) | (unsigned)(~idx);
                    }
                }
            }
        }
        __syncthreads();

        const int cf = min(cand_cnt, CAND_FB);
        for (int i = tid; i < cf; i += NT) {
            unsigned long long ki = u.cand[i];
            int rank2 = 0;
            for (int j = 0; j < cf; j++) rank2 += (u.cand[j] > ki) ? 1 : 0;
            if (rank2 < TOPK) {
                unsigned key = (unsigned)(ki >> 32);
                unsigned idx = ~(unsigned)(ki & 0xFFFFFFFFull);
                float raw = finv(key);
                float sc  = 1.0f / (1.0f + expf(-raw));
                s_score[rank2] = sc;
                s_valid[rank2] = (sc > THRESH) ? 1 : 0;
                int z   = (int)idx / (Hh * Ww);
                int rem = (int)idx % (Hh * Ww);
                int y   = rem / Ww;
                int x   = rem % Ww;
                size_t base3 = (size_t)b * 3 * NA + idx;
                float o0 = Off[base3], o1 = Off[base3 + NA], o2 = Off[base3 + 2 * NA];
                float h0 = Shp[base3], h1 = Shp[base3 + NA], h2 = Shp[base3 + 2 * NA];
                s_ctr[rank2][0] = ((float)z + o0) * 2.0f;
                s_ctr[rank2][1] = ((float)y + o1) * 2.0f;
                s_ctr[rank2][2] = ((float)x + o2) * 2.0f;
                s_ext[rank2][0] = 2.0f * h0;
                s_ext[rank2][1] = 2.0f * h1;
                s_ext[rank2][2] = 2.0f * h2;
            }
        }
        __syncthreads();
        // re-fill output (partner prefill already done, but keep exactness if fallback)
        if (tid < TOPK * 8) ob[tid] = -1.0f;
        __syncthreads();
    }

    // ---- IoU > NMS_T bitmask: 17 strips x 4 cols per row ----
    {
        int i = tid % TOPK;           // row
        int qd = tid / TOPK;          // strip (tid < 1020 -> qd < 17)
        if (qd < 17) {
            float ci0 = s_ctr[i][0], ci1 = s_ctr[i][1], ci2 = s_ctr[i][2];
            float ei0 = s_ext[i][0], ei1 = s_ext[i][1], ei2 = s_ext[i][2];
            float li0 = ci0 - 0.5f * ei0, li1 = ci1 - 0.5f * ei1, li2 = ci2 - 0.5f * ei2;
            float hi0 = ci0 + 0.5f * ei0, hi1 = ci1 + 0.5f * ei1, hi2 = ci2 + 0.5f * ei2;
            float vi  = ei0 * ei1 * ei2;
            unsigned long long m = 0ull;
            int j0 = qd * 4;
            #pragma unroll
            for (int t = 0; t < 4; t++) {
                int j = j0 + t;
                if (j < TOPK) {
                    float ej0 = s_ext[j][0], ej1 = s_ext[j][1], ej2 = s_ext[j][2];
                    float lj0 = s_ctr[j][0] - 0.5f * ej0;
                    float lj1 = s_ctr[j][1] - 0.5f * ej1;
                    float lj2 = s_ctr[j][2] - 0.5f * ej2;
                    float hj0 = s_ctr[j][0] + 0.5f * ej0;
                    float hj1 = s_ctr[j][1] + 0.5f * ej1;
                    float hj2 = s_ctr[j][2] + 0.5f * ej2;
                    float d0 = fminf(hi0, hj0) - fmaxf(li0, lj0);
                    float d1 = fminf(hi1, hj1) - fmaxf(li1, lj1);
                    float d2 = fminf(hi2, hj2) - fmaxf(li2, lj2);
                    float inter = fmaxf(d0, 0.0f) * fmaxf(d1, 0.0f) * fmaxf(d2, 0.0f);
                    float vj  = ej0 * ej1 * ej2;
                    float un  = vi + vj - inter;
                    float iou = inter / fmaxf(un, 1e-8f);
                    if (iou > NMS_T) m |= (1ull << j);
                }
            }
            if (m) atomicOr(&s_mask[i], m);
        }
    }
    __syncthreads();

    // ---- greedy NMS on a u64 mask ----
    if (tid == 0) {
        unsigned long long km = 0ull;
        #pragma unroll 4
        for (int i = 0; i < TOPK; i++)
            if (s_valid[i] && !(s_mask[i] & km)) km |= (1ull << i);
        s_keep = km;
    }
    __syncthreads();

    // ---- write kept rows at their rank (output already -1-filled) ----
    if (tid < TOPK) {
        unsigned long long km = s_keep;
        if ((km >> tid) & 1ull) {
            int rk = __popcll(km & ((1ull << tid) - 1ull));
            if (rk < NMS_TOPK) {
                float* row = ob + (size_t)rk * 8;
                row[0] = 1.0f;
                row[1] = s_score[tid];
                row[2] = s_ctr[tid][0];
                row[3] = s_ctr[tid][1];
                row[4] = s_ctr[tid][2];
                row[5] = s_ext[tid][0];
                row[6] = s_ext[tid][1];
                row[7] = s_ext[tid][2];
            }
        }
    }
}

extern "C" void kernel_launch(void* const* d_in, const int* in_sizes, int n_in,
                              void* d_out, int out_size)
{
    const float* Cls = (const float*)d_in[0];
    const float* Shp = (const float*)d_in[1];
    const float* Off = (const float*)d_in[2];
    float* out = (float*)d_out;

    dim3 grid(2, Bn);        // 128 CTAs, 64 clusters of 2, single wave
    detclu<<<grid, NT>>>(Cls, Shp, Off, out);
}